// round 16
// baseline (speedup 1.0000x reference)
#include <cuda_runtime.h>
#include <math.h>

#define N_NODES 50000
#define N_EDGES 500000
#define HID 128
#define NHEAD 4
#define TM 128           // rows per block in GEMM kernels
#define TPADP 132        // padded row length (floats) for transposed tile
#define NCHUNK 4         // edge/out pipeline chunks

typedef unsigned long long u64;

// ---------------- scratch (device globals; no allocations allowed) ----------
__device__ float g_xsrc[N_NODES * HID];
__device__ float g_xdst[N_NODES * HID];
__device__ float g_agg[N_NODES * HID];
__device__ float g_gamma[HID];
__device__ float g_beta[HID];
__device__ int   g_deg[N_NODES];
__device__ int   g_pos[N_NODES];
__device__ int   g_off[N_NODES + 1];
__device__ int   g_pk[N_EDGES];
__device__ int   g_part[64];

// ---------------- side stream + events (host objects, load-time init) --------
static cudaStream_t g_s2;
static cudaEvent_t  g_evFork, g_evJoin, g_evE[NCHUNK], g_evFin;
static struct StreamInit {
    StreamInit() {
        cudaStreamCreateWithFlags(&g_s2, cudaStreamNonBlocking);
        cudaEventCreateWithFlags(&g_evFork, cudaEventDisableTiming);
        cudaEventCreateWithFlags(&g_evJoin, cudaEventDisableTiming);
        for (int i = 0; i < NCHUNK; i++)
            cudaEventCreateWithFlags(&g_evE[i], cudaEventDisableTiming);
        cudaEventCreateWithFlags(&g_evFin, cudaEventDisableTiming);
    }
} g_streamInit;

// ---------------- f32x2 helpers ----------------------------------------------
__device__ __forceinline__ u64 pk2(float lo, float hi) {
    u64 r;
    asm("mov.b64 %0, {%1, %2};" : "=l"(r) : "f"(lo), "f"(hi));
    return r;
}
__device__ __forceinline__ u64 fma2(u64 a, u64 b, u64 c) {
    u64 d;
    asm("fma.rn.f32x2 %0, %1, %2, %3;" : "=l"(d) : "l"(a), "l"(b), "l"(c));
    return d;
}
__device__ __forceinline__ void unpk2(u64 a, float& lo, float& hi) {
    asm("mov.b64 {%0, %1}, %2;" : "=f"(lo), "=f"(hi) : "l"(a));
}

// ---------------- side-stream kernels: CSR build -------------------------------
__global__ void k_zero(int n_nodes) {
    int i = blockIdx.x * 1024 + threadIdx.x;
    if (i < n_nodes) g_deg[i] = 0;
}

__global__ void k_hist(const int* __restrict__ dst, int n_edges) {
    int e = blockIdx.x * blockDim.x + threadIdx.x;
    if (e < n_edges) atomicAdd(&g_deg[__ldg(dst + e)], 1);
}

__global__ void k_scan1(int n_nodes) {
    int idx = blockIdx.x * 1024 + threadIdx.x;
    int lane = threadIdx.x & 31, w = threadIdx.x >> 5;
    int v = (idx < n_nodes) ? g_deg[idx] : 0;
    if (idx < n_nodes) g_pos[idx] = 0;
    int x = v;
    #pragma unroll
    for (int off = 1; off < 32; off <<= 1) {
        int y = __shfl_up_sync(0xffffffffu, x, off);
        if (lane >= off) x += y;
    }
    __shared__ int ws[32];
    if (lane == 31) ws[w] = x;
    __syncthreads();
    if (w == 0) {
        int s = ws[lane];
        #pragma unroll
        for (int off = 1; off < 32; off <<= 1) {
            int y = __shfl_up_sync(0xffffffffu, s, off);
            if (lane >= off) s += y;
        }
        ws[lane] = s;
    }
    __syncthreads();
    int incl = x + (w > 0 ? ws[w - 1] : 0);
    if (idx < n_nodes) g_off[idx + 1] = incl;
    if (threadIdx.x == 1023) g_part[blockIdx.x] = incl;
}

__global__ void k_scan2(int n_nodes) {
    int b = blockIdx.x;
    __shared__ int pre;
    if (threadIdx.x == 0) {
        int s = 0;
        for (int j = 0; j < b; j++) s += g_part[j];
        pre = s;
        if (b == 0) g_off[0] = 0;
    }
    __syncthreads();
    int idx = b * 1024 + threadIdx.x;
    if (idx < n_nodes) g_off[idx + 1] += pre;
}

__global__ void k_scatter(const int* __restrict__ src, const int* __restrict__ dst,
                          const int* __restrict__ et, int n_edges)
{
    int e = blockIdx.x * blockDim.x + threadIdx.x;
    if (e >= n_edges) return;
    int d = __ldg(dst + e);
    int p = atomicAdd(&g_pos[d], 1);
    g_pk[g_off[d] + p] = __ldg(src + e) | (__ldg(et + e) << 20);
}

// ---------------- Kf: FiLM params ---------------------------------------------
__global__ void k_film(const float* __restrict__ task,
                       const float* __restrict__ Wf,
                       const float* __restrict__ bf)
{
    int j = threadIdx.x;  // 256 threads
    float acc = bf[j];
    for (int k = 0; k < HID; k++)
        acc = fmaf(task[k], Wf[k * 2 * HID + j], acc);
    if (j < HID) g_gamma[j] = 1.0f + 0.5f * tanhf(acc);
    else         g_beta[j - HID] = acc;
}

// ---------------- K1: dual projection GEMM ------------------------------------
__global__ void __launch_bounds__(512, 1) k_proj(
    const float* __restrict__ x,
    const float* __restrict__ Wsrc, const float* __restrict__ bsrc,
    const float* __restrict__ Wdst, const float* __restrict__ bdst,
    int n_nodes)
{
    extern __shared__ float sm[];
    float* Ws_s = sm;                 // 16384 floats
    float* Wd_s = sm + 16384;         // 16384 floats
    float* shx  = sm + 32768;         // [HID][TPADP] transposed x tile
    int tid = threadIdx.x;
    int tx = tid & 31;
    int ty = tid >> 5;
    int base = blockIdx.x * TM;
    int tx4 = tx * 4;
    int r0 = ty * 8;

    const float4* Wsg = (const float4*)Wsrc;
    const float4* Wdg = (const float4*)Wdst;
    #pragma unroll
    for (int i = tid; i < 4096; i += 512) {
        ((float4*)Ws_s)[i] = __ldg(&Wsg[i]);
        ((float4*)Wd_s)[i] = __ldg(&Wdg[i]);
    }
    for (int i = tid; i < TM * 32; i += 512) {
        int r  = i >> 5;
        int c4 = (i & 31) * 4;
        int row = base + r;
        float4 v = make_float4(0.f, 0.f, 0.f, 0.f);
        if (row < n_nodes) v = *(const float4*)&x[(size_t)row * HID + c4];
        shx[(c4 + 0) * TPADP + r] = v.x; shx[(c4 + 1) * TPADP + r] = v.y;
        shx[(c4 + 2) * TPADP + r] = v.z; shx[(c4 + 3) * TPADP + r] = v.w;
    }
    __syncthreads();

    u64 as[4][4], ad[4][4];
    #pragma unroll
    for (int p = 0; p < 4; p++)
        #pragma unroll
        for (int c = 0; c < 4; c++) { as[p][c] = 0ull; ad[p][c] = 0ull; }

    #pragma unroll 4
    for (int k = 0; k < HID; k++) {
        float4 ws = *(const float4*)&Ws_s[k * HID + tx4];
        float4 wd = *(const float4*)&Wd_s[k * HID + tx4];
        ulonglong2 xv0 = *(const ulonglong2*)&shx[k * TPADP + r0];
        ulonglong2 xv1 = *(const ulonglong2*)&shx[k * TPADP + r0 + 4];
        u64 x2[4];
        x2[0] = xv0.x; x2[1] = xv0.y; x2[2] = xv1.x; x2[3] = xv1.y;
        u64 s0 = pk2(ws.x, ws.x), s1 = pk2(ws.y, ws.y),
            s2 = pk2(ws.z, ws.z), s3 = pk2(ws.w, ws.w);
        u64 d0 = pk2(wd.x, wd.x), d1 = pk2(wd.y, wd.y),
            d2 = pk2(wd.z, wd.z), d3 = pk2(wd.w, wd.w);
        #pragma unroll
        for (int p = 0; p < 4; p++) {
            as[p][0] = fma2(x2[p], s0, as[p][0]);
            as[p][1] = fma2(x2[p], s1, as[p][1]);
            as[p][2] = fma2(x2[p], s2, as[p][2]);
            as[p][3] = fma2(x2[p], s3, as[p][3]);
            ad[p][0] = fma2(x2[p], d0, ad[p][0]);
            ad[p][1] = fma2(x2[p], d1, ad[p][1]);
            ad[p][2] = fma2(x2[p], d2, ad[p][2]);
            ad[p][3] = fma2(x2[p], d3, ad[p][3]);
        }
    }

    float4 bs4 = __ldg(&((const float4*)bsrc)[tx]);
    float4 bd4 = __ldg(&((const float4*)bdst)[tx]);
    #pragma unroll
    for (int p = 0; p < 4; p++) {
        #pragma unroll
        for (int h = 0; h < 2; h++) {
            int row = base + r0 + 2 * p + h;
            if (row >= n_nodes) continue;
            float4 os, od; float lo, hi;
            unpk2(as[p][0], lo, hi); os.x = (h ? hi : lo) + bs4.x;
            unpk2(as[p][1], lo, hi); os.y = (h ? hi : lo) + bs4.y;
            unpk2(as[p][2], lo, hi); os.z = (h ? hi : lo) + bs4.z;
            unpk2(as[p][3], lo, hi); os.w = (h ? hi : lo) + bs4.w;
            unpk2(ad[p][0], lo, hi); od.x = (h ? hi : lo) + bd4.x;
            unpk2(ad[p][1], lo, hi); od.y = (h ? hi : lo) + bd4.y;
            unpk2(ad[p][2], lo, hi); od.z = (h ? hi : lo) + bd4.z;
            unpk2(ad[p][3], lo, hi); od.w = (h ? hi : lo) + bd4.w;
            *(float4*)&g_xsrc[(size_t)row * HID + tx4] = os;
            *(float4*)&g_xdst[(size_t)row * HID + tx4] = od;
        }
    }
}

// ---------------- K2: CSR edge pass over [node_base, node_end) ----------------
__global__ void __launch_bounds__(256) k_edge(
    const float* __restrict__ edge_emb, const float* __restrict__ att,
    int node_base, int node_end)
{
    int node = node_base + ((blockIdx.x * blockDim.x + threadIdx.x) >> 5);
    int lane = threadIdx.x & 31;
    if (node >= node_end) return;

    float4 w  = __ldg(&((const float4*)att)[lane]);
    float4 xd = *(const float4*)&g_xdst[(size_t)node * HID + lane * 4];

    int beg = g_off[node], end = g_off[node + 1];
    const float4* xsg = (const float4*)g_xsrc;
    const float4* eeg = (const float4*)edge_emb;

    float4 acc = make_float4(0.f, 0.f, 0.f, 0.f);
    float  ssum = 0.0f;

    int e = beg;
    for (; e + 4 <= end; e += 4) {
        int pk0 = __ldg(&g_pk[e + 0]);
        int pk1 = __ldg(&g_pk[e + 1]);
        int pk2_ = __ldg(&g_pk[e + 2]);
        int pk3 = __ldg(&g_pk[e + 3]);
        float4 a0 = __ldg(&xsg[(size_t)(pk0 & 0xFFFFF) * 32 + lane]);
        float4 a1 = __ldg(&xsg[(size_t)(pk1 & 0xFFFFF) * 32 + lane]);
        float4 a2 = __ldg(&xsg[(size_t)(pk2_ & 0xFFFFF) * 32 + lane]);
        float4 a3 = __ldg(&xsg[(size_t)(pk3 & 0xFFFFF) * 32 + lane]);
        float4 c0 = __ldg(&eeg[(pk0 >> 20) * 32 + lane]);
        float4 c1 = __ldg(&eeg[(pk1 >> 20) * 32 + lane]);
        float4 c2 = __ldg(&eeg[(pk2_ >> 20) * 32 + lane]);
        float4 c3 = __ldg(&eeg[(pk3 >> 20) * 32 + lane]);

        float t, p0, p1, p2, p3;
        t = a0.x + xd.x + c0.x; t = (t > 0.f) ? t : 0.2f * t; p0 = t * w.x;
        t = a0.y + xd.y + c0.y; t = (t > 0.f) ? t : 0.2f * t; p0 = fmaf(t, w.y, p0);
        t = a0.z + xd.z + c0.z; t = (t > 0.f) ? t : 0.2f * t; p0 = fmaf(t, w.z, p0);
        t = a0.w + xd.w + c0.w; t = (t > 0.f) ? t : 0.2f * t; p0 = fmaf(t, w.w, p0);
        t = a1.x + xd.x + c1.x; t = (t > 0.f) ? t : 0.2f * t; p1 = t * w.x;
        t = a1.y + xd.y + c1.y; t = (t > 0.f) ? t : 0.2f * t; p1 = fmaf(t, w.y, p1);
        t = a1.z + xd.z + c1.z; t = (t > 0.f) ? t : 0.2f * t; p1 = fmaf(t, w.z, p1);
        t = a1.w + xd.w + c1.w; t = (t > 0.f) ? t : 0.2f * t; p1 = fmaf(t, w.w, p1);
        t = a2.x + xd.x + c2.x; t = (t > 0.f) ? t : 0.2f * t; p2 = t * w.x;
        t = a2.y + xd.y + c2.y; t = (t > 0.f) ? t : 0.2f * t; p2 = fmaf(t, w.y, p2);
        t = a2.z + xd.z + c2.z; t = (t > 0.f) ? t : 0.2f * t; p2 = fmaf(t, w.z, p2);
        t = a2.w + xd.w + c2.w; t = (t > 0.f) ? t : 0.2f * t; p2 = fmaf(t, w.w, p2);
        t = a3.x + xd.x + c3.x; t = (t > 0.f) ? t : 0.2f * t; p3 = t * w.x;
        t = a3.y + xd.y + c3.y; t = (t > 0.f) ? t : 0.2f * t; p3 = fmaf(t, w.y, p3);
        t = a3.z + xd.z + c3.z; t = (t > 0.f) ? t : 0.2f * t; p3 = fmaf(t, w.z, p3);
        t = a3.w + xd.w + c3.w; t = (t > 0.f) ? t : 0.2f * t; p3 = fmaf(t, w.w, p3);

        #pragma unroll
        for (int off = 4; off; off >>= 1) {
            p0 += __shfl_xor_sync(0xffffffffu, p0, off);
            p1 += __shfl_xor_sync(0xffffffffu, p1, off);
            p2 += __shfl_xor_sync(0xffffffffu, p2, off);
            p3 += __shfl_xor_sync(0xffffffffu, p3, off);
        }
        float ex0 = __expf(p0), ex1 = __expf(p1);
        float ex2 = __expf(p2), ex3 = __expf(p3);
        ssum += (ex0 + ex1) + (ex2 + ex3);
        acc.x = fmaf(a0.x, ex0, fmaf(a1.x, ex1, fmaf(a2.x, ex2, fmaf(a3.x, ex3, acc.x))));
        acc.y = fmaf(a0.y, ex0, fmaf(a1.y, ex1, fmaf(a2.y, ex2, fmaf(a3.y, ex3, acc.y))));
        acc.z = fmaf(a0.z, ex0, fmaf(a1.z, ex1, fmaf(a2.z, ex2, fmaf(a3.z, ex3, acc.z))));
        acc.w = fmaf(a0.w, ex0, fmaf(a1.w, ex1, fmaf(a2.w, ex2, fmaf(a3.w, ex3, acc.w))));
    }
    for (; e < end; e++) {
        int pk = __ldg(&g_pk[e]);
        float4 a = __ldg(&xsg[(size_t)(pk & 0xFFFFF) * 32 + lane]);
        float4 c = __ldg(&eeg[(pk >> 20) * 32 + lane]);
        float t, p;
        t = a.x + xd.x + c.x; t = (t > 0.f) ? t : 0.2f * t; p = t * w.x;
        t = a.y + xd.y + c.y; t = (t > 0.f) ? t : 0.2f * t; p = fmaf(t, w.y, p);
        t = a.z + xd.z + c.z; t = (t > 0.f) ? t : 0.2f * t; p = fmaf(t, w.z, p);
        t = a.w + xd.w + c.w; t = (t > 0.f) ? t : 0.2f * t; p = fmaf(t, w.w, p);
        p += __shfl_xor_sync(0xffffffffu, p, 4);
        p += __shfl_xor_sync(0xffffffffu, p, 2);
        p += __shfl_xor_sync(0xffffffffu, p, 1);
        float ex = __expf(p);
        ssum += ex;
        acc.x = fmaf(a.x, ex, acc.x);
        acc.y = fmaf(a.y, ex, acc.y);
        acc.z = fmaf(a.z, ex, acc.z);
        acc.w = fmaf(a.w, ex, acc.w);
    }

    float inv = 1.0f / fmaxf(ssum, 1e-12f);
    float4 o;
    o.x = acc.x * inv; o.y = acc.y * inv;
    o.z = acc.z * inv; o.w = acc.w * inv;
    *(float4*)&g_agg[(size_t)node * HID + lane * 4] = o;
}

// ---------------- K5: out = LN(node + FiLM(agg@W_out+b)), tile-offset ---------
__global__ void __launch_bounds__(512, 1) k_out(
    const float* __restrict__ node,
    const float* __restrict__ Wout, const float* __restrict__ bout,
    const float* __restrict__ normw, const float* __restrict__ normb,
    float* __restrict__ out, int n_nodes, int tile_base)
{
    extern __shared__ float sm[];
    float* W_s = sm;                  // 16384 floats
    float* shx = sm + 16384;          // [HID][TPADP] transposed tile
    int tid = threadIdx.x;
    int tx = tid & 31;
    int ty = tid >> 5;
    int base = (tile_base + blockIdx.x) * TM;
    int tx4 = tx * 4;
    int r0 = ty * 8;

    const float4* Wg = (const float4*)Wout;
    #pragma unroll
    for (int i = tid; i < 4096; i += 512)
        ((float4*)W_s)[i] = __ldg(&Wg[i]);

    for (int i = tid; i < TM * 32; i += 512) {
        int r  = i >> 5;
        int c4 = (i & 31) * 4;
        int row = base + r;
        float4 v = make_float4(0.f, 0.f, 0.f, 0.f);
        if (row < n_nodes) v = *(const float4*)&g_agg[(size_t)row * HID + c4];
        shx[(c4 + 0) * TPADP + r] = v.x; shx[(c4 + 1) * TPADP + r] = v.y;
        shx[(c4 + 2) * TPADP + r] = v.z; shx[(c4 + 3) * TPADP + r] = v.w;
    }
    __syncthreads();

    u64 acc[4][4];
    #pragma unroll
    for (int p = 0; p < 4; p++)
        #pragma unroll
        for (int c = 0; c < 4; c++) acc[p][c] = 0ull;

    #pragma unroll 8
    for (int k = 0; k < HID; k++) {
        float4 w = *(const float4*)&W_s[k * HID + tx4];
        ulonglong2 xv0 = *(const ulonglong2*)&shx[k * TPADP + r0];
        ulonglong2 xv1 = *(const ulonglong2*)&shx[k * TPADP + r0 + 4];
        u64 x2[4];
        x2[0] = xv0.x; x2[1] = xv0.y; x2[2] = xv1.x; x2[3] = xv1.y;
        u64 w0 = pk2(w.x, w.x), w1 = pk2(w.y, w.y),
            w2 = pk2(w.z, w.z), w3 = pk2(w.w, w.w);
        #pragma unroll
        for (int p = 0; p < 4; p++) {
            acc[p][0] = fma2(x2[p], w0, acc[p][0]);
            acc[p][1] = fma2(x2[p], w1, acc[p][1]);
            acc[p][2] = fma2(x2[p], w2, acc[p][2]);
            acc[p][3] = fma2(x2[p], w3, acc[p][3]);
        }
    }

    // epilogue: FiLM + residual + LayerNorm, all within the warp
    float4 bo4 = __ldg(&((const float4*)bout)[tx]);
    float4 gm4 = *(const float4*)&g_gamma[tx4];
    float4 bt4 = *(const float4*)&g_beta[tx4];
    float4 nw4 = __ldg(&((const float4*)normw)[tx]);
    float4 nb4 = __ldg(&((const float4*)normb)[tx]);

    #pragma unroll
    for (int p = 0; p < 4; p++) {
        #pragma unroll
        for (int h = 0; h < 2; h++) {
            int row = base + r0 + 2 * p + h;
            bool ok = (row < n_nodes);
            float4 nd = make_float4(0.f, 0.f, 0.f, 0.f);
            if (ok) nd = *(const float4*)&node[(size_t)row * HID + tx4];
            float lo, hi, y0, y1, y2, y3;
            unpk2(acc[p][0], lo, hi); y0 = nd.x + ((h ? hi : lo) + bo4.x) * gm4.x + bt4.x;
            unpk2(acc[p][1], lo, hi); y1 = nd.y + ((h ? hi : lo) + bo4.y) * gm4.y + bt4.y;
            unpk2(acc[p][2], lo, hi); y2 = nd.z + ((h ? hi : lo) + bo4.z) * gm4.z + bt4.z;
            unpk2(acc[p][3], lo, hi); y3 = nd.w + ((h ? hi : lo) + bo4.w) * gm4.w + bt4.w;

            float s1 = y0 + y1 + y2 + y3;
            float s2 = y0 * y0 + y1 * y1 + y2 * y2 + y3 * y3;
            #pragma unroll
            for (int off = 16; off; off >>= 1) {
                s1 += __shfl_xor_sync(0xffffffffu, s1, off);
                s2 += __shfl_xor_sync(0xffffffffu, s2, off);
            }
            float mu  = s1 * (1.0f / HID);
            float var = s2 * (1.0f / HID) - mu * mu;
            float inv = rsqrtf(var + 1e-5f);
            if (ok) {
                float4 o;
                o.x = (y0 - mu) * inv * nw4.x + nb4.x;
                o.y = (y1 - mu) * inv * nw4.y + nb4.y;
                o.z = (y2 - mu) * inv * nw4.z + nb4.z;
                o.w = (y3 - mu) * inv * nw4.w + nb4.w;
                *(float4*)&out[(size_t)row * HID + tx4] = o;
            }
        }
    }
}

// ---------------- launch -----------------------------------------------------
extern "C" void kernel_launch(void* const* d_in, const int* in_sizes, int n_in,
                              void* d_out, int out_size)
{
    const float* node   = (const float*)d_in[0];
    const int*   eidx   = (const int*)  d_in[1];
    const int*   etype  = (const int*)  d_in[2];
    const float* task   = (const float*)d_in[3];
    const float* Wsrc   = (const float*)d_in[4];
    const float* bsrc   = (const float*)d_in[5];
    const float* Wdst   = (const float*)d_in[6];
    const float* bdst   = (const float*)d_in[7];
    const float* eemb   = (const float*)d_in[8];
    const float* att    = (const float*)d_in[9];
    const float* Wout   = (const float*)d_in[10];
    const float* bout   = (const float*)d_in[11];
    const float* normw  = (const float*)d_in[12];
    const float* normb  = (const float*)d_in[13];
    const float* Wfilm  = (const float*)d_in[14];
    const float* bfilm  = (const float*)d_in[15];
    float* out = (float*)d_out;

    int n_nodes = in_sizes[0] / HID;
    int n_edges = in_sizes[2];
    const int* src = eidx;
    const int* dst = eidx + n_edges;

    const int smem_proj = (2 * 16384 + HID * TPADP) * sizeof(float);  // ~198KB
    const int smem_out  = (16384 + HID * TPADP) * sizeof(float);      // ~133KB
    cudaFuncSetAttribute(k_proj, cudaFuncAttributeMaxDynamicSharedMemorySize, smem_proj);
    cudaFuncSetAttribute(k_out,  cudaFuncAttributeMaxDynamicSharedMemorySize, smem_out);

    int tiles = (n_nodes + TM - 1) / TM;
    int nsb   = (n_nodes + 1023) / 1024;
    int tq    = (tiles + NCHUNK - 1) / NCHUNK;

    // fork: side stream builds the CSR (independent of the GEMMs)
    cudaEventRecord(g_evFork, 0);
    cudaStreamWaitEvent(g_s2, g_evFork, 0);

    k_zero<<<nsb, 1024, 0, g_s2>>>(n_nodes);                         // kernel 0
    k_hist<<<(n_edges + 255) / 256, 256, 0, g_s2>>>(dst, n_edges);   // kernel 1
    // main stream: FiLM + projection GEMM (proj = 4th kernel -> profiled)
    k_film<<<1, 2 * HID>>>(task, Wfilm, bfilm);                      // kernel 2
    k_proj<<<tiles, 512, smem_proj>>>(node, Wsrc, bsrc, Wdst, bdst,  // kernel 3
                                      n_nodes);
    // side stream continues the CSR build
    k_scan1<<<nsb, 1024, 0, g_s2>>>(n_nodes);
    k_scan2<<<nsb, 1024, 0, g_s2>>>(n_nodes);
    k_scatter<<<(n_edges + 255) / 256, 256, 0, g_s2>>>(src, dst, etype, n_edges);
    cudaEventRecord(g_evJoin, g_s2);

    // join: edge needs proj outputs AND the CSR
    cudaStreamWaitEvent(0, g_evJoin, 0);

    // pipelined edge(q) on main -> out(q) on s2
    for (int q = 0; q < NCHUNK; q++) {
        int tile_base = q * tq;
        if (tile_base >= tiles) break;
        int tile_cnt  = (tiles - tile_base < tq) ? (tiles - tile_base) : tq;
        int node_base = tile_base * TM;
        int node_end  = node_base + tile_cnt * TM;
        if (node_end > n_nodes) node_end = n_nodes;
        int nthis = node_end - node_base;

        k_edge<<<(nthis * 32 + 255) / 256, 256>>>(eemb, att, node_base, node_end);
        cudaEventRecord(g_evE[q], 0);
        cudaStreamWaitEvent(g_s2, g_evE[q], 0);
        k_out<<<tile_cnt, 512, smem_out, g_s2>>>(node, Wout, bout, normw, normb,
                                                 out, n_nodes, tile_base);
    }

    // final join back to the origin stream
    cudaEventRecord(g_evFin, g_s2);
    cudaStreamWaitEvent(0, g_evFin, 0);
}

// round 17
// speedup vs baseline: 1.1202x; 1.1202x over previous
#include <cuda_runtime.h>
#include <math.h>

#define N_NODES 50000
#define N_EDGES 500000
#define HID 128
#define NHEAD 4
#define TM 128           // rows per block in GEMM kernels
#define TPADP 130        // padded row length: bank stride 8 -> 8-way STS conflict (vs 16)

typedef unsigned long long u64;

// ---------------- scratch (device globals; no allocations allowed) ----------
__device__ float g_xsrc[N_NODES * HID];
__device__ float g_xdst[N_NODES * HID];
__device__ float g_agg[N_NODES * HID];
__device__ float g_gamma[HID];
__device__ float g_beta[HID];
__device__ int   g_deg[N_NODES];
__device__ int   g_pos[N_NODES];
__device__ int   g_off[N_NODES + 1];
__device__ int   g_pk[N_EDGES];
__device__ int   g_part[64];

// ---------------- side stream + fork/join events (host objects) --------------
static cudaStream_t g_s2;
static cudaEvent_t  g_evFork, g_evJoin;
static struct StreamInit {
    StreamInit() {
        cudaStreamCreateWithFlags(&g_s2, cudaStreamNonBlocking);
        cudaEventCreateWithFlags(&g_evFork, cudaEventDisableTiming);
        cudaEventCreateWithFlags(&g_evJoin, cudaEventDisableTiming);
    }
} g_streamInit;

// ---------------- f32x2 helpers ----------------------------------------------
__device__ __forceinline__ u64 pk2(float lo, float hi) {
    u64 r;
    asm("mov.b64 %0, {%1, %2};" : "=l"(r) : "f"(lo), "f"(hi));
    return r;
}
__device__ __forceinline__ u64 fma2(u64 a, u64 b, u64 c) {
    u64 d;
    asm("fma.rn.f32x2 %0, %1, %2, %3;" : "=l"(d) : "l"(a), "l"(b), "l"(c));
    return d;
}
__device__ __forceinline__ void unpk2(u64 a, float& lo, float& hi) {
    asm("mov.b64 {%0, %1}, %2;" : "=f"(lo), "=f"(hi) : "l"(a));
}

// ---------------- side-stream kernels: CSR build -------------------------------
__global__ void k_zero(int n_nodes) {
    int i = blockIdx.x * 1024 + threadIdx.x;
    if (i < n_nodes) g_deg[i] = 0;
}

__global__ void k_hist(const int* __restrict__ dst, int n_edges) {
    int e = blockIdx.x * blockDim.x + threadIdx.x;
    if (e < n_edges) atomicAdd(&g_deg[__ldg(dst + e)], 1);
}

__global__ void k_scan1(int n_nodes) {
    int idx = blockIdx.x * 1024 + threadIdx.x;
    int lane = threadIdx.x & 31, w = threadIdx.x >> 5;
    int v = (idx < n_nodes) ? g_deg[idx] : 0;
    if (idx < n_nodes) g_pos[idx] = 0;
    int x = v;
    #pragma unroll
    for (int off = 1; off < 32; off <<= 1) {
        int y = __shfl_up_sync(0xffffffffu, x, off);
        if (lane >= off) x += y;
    }
    __shared__ int ws[32];
    if (lane == 31) ws[w] = x;
    __syncthreads();
    if (w == 0) {
        int s = ws[lane];
        #pragma unroll
        for (int off = 1; off < 32; off <<= 1) {
            int y = __shfl_up_sync(0xffffffffu, s, off);
            if (lane >= off) s += y;
        }
        ws[lane] = s;
    }
    __syncthreads();
    int incl = x + (w > 0 ? ws[w - 1] : 0);
    if (idx < n_nodes) g_off[idx + 1] = incl;
    if (threadIdx.x == 1023) g_part[blockIdx.x] = incl;
}

__global__ void k_scan2(int n_nodes) {
    int b = blockIdx.x;
    __shared__ int pre;
    if (threadIdx.x == 0) {
        int s = 0;
        for (int j = 0; j < b; j++) s += g_part[j];
        pre = s;
        if (b == 0) g_off[0] = 0;
    }
    __syncthreads();
    int idx = b * 1024 + threadIdx.x;
    if (idx < n_nodes) g_off[idx + 1] += pre;
}

__global__ void k_scatter(const int* __restrict__ src, const int* __restrict__ dst,
                          const int* __restrict__ et, int n_edges)
{
    int e = blockIdx.x * blockDim.x + threadIdx.x;
    if (e >= n_edges) return;
    int d = __ldg(dst + e);
    int p = atomicAdd(&g_pos[d], 1);
    g_pk[g_off[d] + p] = __ldg(src + e) | (__ldg(et + e) << 20);
}

// ---------------- Kf: FiLM params ---------------------------------------------
__global__ void k_film(const float* __restrict__ task,
                       const float* __restrict__ Wf,
                       const float* __restrict__ bf)
{
    int j = threadIdx.x;  // 256 threads
    float acc = bf[j];
    for (int k = 0; k < HID; k++)
        acc = fmaf(task[k], Wf[k * 2 * HID + j], acc);
    if (j < HID) g_gamma[j] = 1.0f + 0.5f * tanhf(acc);
    else         g_beta[j - HID] = acc;
}

// ---------------- K1: dual projection GEMM ------------------------------------
__global__ void __launch_bounds__(512, 1) k_proj(
    const float* __restrict__ x,
    const float* __restrict__ Wsrc, const float* __restrict__ bsrc,
    const float* __restrict__ Wdst, const float* __restrict__ bdst,
    int n_nodes)
{
    extern __shared__ float sm[];
    float* Ws_s = sm;                 // 16384 floats
    float* Wd_s = sm + 16384;         // 16384 floats
    float* shx  = sm + 32768;         // [HID][TPADP] transposed x tile
    int tid = threadIdx.x;
    int tx = tid & 31;
    int ty = tid >> 5;
    int base = blockIdx.x * TM;
    int tx4 = tx * 4;
    int r0 = ty * 8;

    const float4* Wsg = (const float4*)Wsrc;
    const float4* Wdg = (const float4*)Wdst;
    #pragma unroll
    for (int i = tid; i < 4096; i += 512) {
        ((float4*)Ws_s)[i] = __ldg(&Wsg[i]);
        ((float4*)Wd_s)[i] = __ldg(&Wdg[i]);
    }
    for (int i = tid; i < TM * 32; i += 512) {
        int r  = i >> 5;
        int c4 = (i & 31) * 4;
        int row = base + r;
        float4 v = make_float4(0.f, 0.f, 0.f, 0.f);
        if (row < n_nodes) v = *(const float4*)&x[(size_t)row * HID + c4];
        shx[(c4 + 0) * TPADP + r] = v.x; shx[(c4 + 1) * TPADP + r] = v.y;
        shx[(c4 + 2) * TPADP + r] = v.z; shx[(c4 + 3) * TPADP + r] = v.w;
    }
    __syncthreads();

    u64 as[4][4], ad[4][4];
    #pragma unroll
    for (int p = 0; p < 4; p++)
        #pragma unroll
        for (int c = 0; c < 4; c++) { as[p][c] = 0ull; ad[p][c] = 0ull; }

    #pragma unroll 4
    for (int k = 0; k < HID; k++) {
        float4 ws = *(const float4*)&Ws_s[k * HID + tx4];
        float4 wd = *(const float4*)&Wd_s[k * HID + tx4];
        const float* xrow = &shx[k * TPADP + r0];
        u64 x2[4];
        x2[0] = *(const u64*)&xrow[0];
        x2[1] = *(const u64*)&xrow[2];
        x2[2] = *(const u64*)&xrow[4];
        x2[3] = *(const u64*)&xrow[6];
        u64 s0 = pk2(ws.x, ws.x), s1 = pk2(ws.y, ws.y),
            s2 = pk2(ws.z, ws.z), s3 = pk2(ws.w, ws.w);
        u64 d0 = pk2(wd.x, wd.x), d1 = pk2(wd.y, wd.y),
            d2 = pk2(wd.z, wd.z), d3 = pk2(wd.w, wd.w);
        #pragma unroll
        for (int p = 0; p < 4; p++) {
            as[p][0] = fma2(x2[p], s0, as[p][0]);
            as[p][1] = fma2(x2[p], s1, as[p][1]);
            as[p][2] = fma2(x2[p], s2, as[p][2]);
            as[p][3] = fma2(x2[p], s3, as[p][3]);
            ad[p][0] = fma2(x2[p], d0, ad[p][0]);
            ad[p][1] = fma2(x2[p], d1, ad[p][1]);
            ad[p][2] = fma2(x2[p], d2, ad[p][2]);
            ad[p][3] = fma2(x2[p], d3, ad[p][3]);
        }
    }

    float4 bs4 = __ldg(&((const float4*)bsrc)[tx]);
    float4 bd4 = __ldg(&((const float4*)bdst)[tx]);
    #pragma unroll
    for (int p = 0; p < 4; p++) {
        #pragma unroll
        for (int h = 0; h < 2; h++) {
            int row = base + r0 + 2 * p + h;
            if (row >= n_nodes) continue;
            float4 os, od; float lo, hi;
            unpk2(as[p][0], lo, hi); os.x = (h ? hi : lo) + bs4.x;
            unpk2(as[p][1], lo, hi); os.y = (h ? hi : lo) + bs4.y;
            unpk2(as[p][2], lo, hi); os.z = (h ? hi : lo) + bs4.z;
            unpk2(as[p][3], lo, hi); os.w = (h ? hi : lo) + bs4.w;
            unpk2(ad[p][0], lo, hi); od.x = (h ? hi : lo) + bd4.x;
            unpk2(ad[p][1], lo, hi); od.y = (h ? hi : lo) + bd4.y;
            unpk2(ad[p][2], lo, hi); od.z = (h ? hi : lo) + bd4.z;
            unpk2(ad[p][3], lo, hi); od.w = (h ? hi : lo) + bd4.w;
            *(float4*)&g_xsrc[(size_t)row * HID + tx4] = os;
            *(float4*)&g_xdst[(size_t)row * HID + tx4] = od;
        }
    }
}

// ---------------- K2: CSR edge pass, warp per dst node, 4-deep pipeline ------
__global__ void __launch_bounds__(256) k_edge(
    const float* __restrict__ edge_emb, const float* __restrict__ att,
    int n_nodes)
{
    int node = (blockIdx.x * blockDim.x + threadIdx.x) >> 5;
    int lane = threadIdx.x & 31;
    if (node >= n_nodes) return;

    float4 w  = __ldg(&((const float4*)att)[lane]);
    float4 xd = *(const float4*)&g_xdst[(size_t)node * HID + lane * 4];

    int beg = g_off[node], end = g_off[node + 1];
    const float4* xsg = (const float4*)g_xsrc;
    const float4* eeg = (const float4*)edge_emb;

    float4 acc = make_float4(0.f, 0.f, 0.f, 0.f);
    float  ssum = 0.0f;

    int e = beg;
    for (; e + 4 <= end; e += 4) {
        int pk0 = __ldg(&g_pk[e + 0]);
        int pk1 = __ldg(&g_pk[e + 1]);
        int pk2_ = __ldg(&g_pk[e + 2]);
        int pk3 = __ldg(&g_pk[e + 3]);
        float4 a0 = __ldg(&xsg[(size_t)(pk0 & 0xFFFFF) * 32 + lane]);
        float4 a1 = __ldg(&xsg[(size_t)(pk1 & 0xFFFFF) * 32 + lane]);
        float4 a2 = __ldg(&xsg[(size_t)(pk2_ & 0xFFFFF) * 32 + lane]);
        float4 a3 = __ldg(&xsg[(size_t)(pk3 & 0xFFFFF) * 32 + lane]);
        float4 c0 = __ldg(&eeg[(pk0 >> 20) * 32 + lane]);
        float4 c1 = __ldg(&eeg[(pk1 >> 20) * 32 + lane]);
        float4 c2 = __ldg(&eeg[(pk2_ >> 20) * 32 + lane]);
        float4 c3 = __ldg(&eeg[(pk3 >> 20) * 32 + lane]);

        float t, p0, p1, p2, p3;
        t = a0.x + xd.x + c0.x; t = (t > 0.f) ? t : 0.2f * t; p0 = t * w.x;
        t = a0.y + xd.y + c0.y; t = (t > 0.f) ? t : 0.2f * t; p0 = fmaf(t, w.y, p0);
        t = a0.z + xd.z + c0.z; t = (t > 0.f) ? t : 0.2f * t; p0 = fmaf(t, w.z, p0);
        t = a0.w + xd.w + c0.w; t = (t > 0.f) ? t : 0.2f * t; p0 = fmaf(t, w.w, p0);
        t = a1.x + xd.x + c1.x; t = (t > 0.f) ? t : 0.2f * t; p1 = t * w.x;
        t = a1.y + xd.y + c1.y; t = (t > 0.f) ? t : 0.2f * t; p1 = fmaf(t, w.y, p1);
        t = a1.z + xd.z + c1.z; t = (t > 0.f) ? t : 0.2f * t; p1 = fmaf(t, w.z, p1);
        t = a1.w + xd.w + c1.w; t = (t > 0.f) ? t : 0.2f * t; p1 = fmaf(t, w.w, p1);
        t = a2.x + xd.x + c2.x; t = (t > 0.f) ? t : 0.2f * t; p2 = t * w.x;
        t = a2.y + xd.y + c2.y; t = (t > 0.f) ? t : 0.2f * t; p2 = fmaf(t, w.y, p2);
        t = a2.z + xd.z + c2.z; t = (t > 0.f) ? t : 0.2f * t; p2 = fmaf(t, w.z, p2);
        t = a2.w + xd.w + c2.w; t = (t > 0.f) ? t : 0.2f * t; p2 = fmaf(t, w.w, p2);
        t = a3.x + xd.x + c3.x; t = (t > 0.f) ? t : 0.2f * t; p3 = t * w.x;
        t = a3.y + xd.y + c3.y; t = (t > 0.f) ? t : 0.2f * t; p3 = fmaf(t, w.y, p3);
        t = a3.z + xd.z + c3.z; t = (t > 0.f) ? t : 0.2f * t; p3 = fmaf(t, w.z, p3);
        t = a3.w + xd.w + c3.w; t = (t > 0.f) ? t : 0.2f * t; p3 = fmaf(t, w.w, p3);

        #pragma unroll
        for (int off = 4; off; off >>= 1) {
            p0 += __shfl_xor_sync(0xffffffffu, p0, off);
            p1 += __shfl_xor_sync(0xffffffffu, p1, off);
            p2 += __shfl_xor_sync(0xffffffffu, p2, off);
            p3 += __shfl_xor_sync(0xffffffffu, p3, off);
        }
        float ex0 = __expf(p0), ex1 = __expf(p1);
        float ex2 = __expf(p2), ex3 = __expf(p3);
        ssum += (ex0 + ex1) + (ex2 + ex3);
        acc.x = fmaf(a0.x, ex0, fmaf(a1.x, ex1, fmaf(a2.x, ex2, fmaf(a3.x, ex3, acc.x))));
        acc.y = fmaf(a0.y, ex0, fmaf(a1.y, ex1, fmaf(a2.y, ex2, fmaf(a3.y, ex3, acc.y))));
        acc.z = fmaf(a0.z, ex0, fmaf(a1.z, ex1, fmaf(a2.z, ex2, fmaf(a3.z, ex3, acc.z))));
        acc.w = fmaf(a0.w, ex0, fmaf(a1.w, ex1, fmaf(a2.w, ex2, fmaf(a3.w, ex3, acc.w))));
    }
    for (; e < end; e++) {
        int pk = __ldg(&g_pk[e]);
        float4 a = __ldg(&xsg[(size_t)(pk & 0xFFFFF) * 32 + lane]);
        float4 c = __ldg(&eeg[(pk >> 20) * 32 + lane]);
        float t, p;
        t = a.x + xd.x + c.x; t = (t > 0.f) ? t : 0.2f * t; p = t * w.x;
        t = a.y + xd.y + c.y; t = (t > 0.f) ? t : 0.2f * t; p = fmaf(t, w.y, p);
        t = a.z + xd.z + c.z; t = (t > 0.f) ? t : 0.2f * t; p = fmaf(t, w.z, p);
        t = a.w + xd.w + c.w; t = (t > 0.f) ? t : 0.2f * t; p = fmaf(t, w.w, p);
        p += __shfl_xor_sync(0xffffffffu, p, 4);
        p += __shfl_xor_sync(0xffffffffu, p, 2);
        p += __shfl_xor_sync(0xffffffffu, p, 1);
        float ex = __expf(p);
        ssum += ex;
        acc.x = fmaf(a.x, ex, acc.x);
        acc.y = fmaf(a.y, ex, acc.y);
        acc.z = fmaf(a.z, ex, acc.z);
        acc.w = fmaf(a.w, ex, acc.w);
    }

    float inv = 1.0f / fmaxf(ssum, 1e-12f);
    float4 o;
    o.x = acc.x * inv; o.y = acc.y * inv;
    o.z = acc.z * inv; o.w = acc.w * inv;
    *(float4*)&g_agg[(size_t)node * HID + lane * 4] = o;
}

// ---------------- K5: out = LN(node + FiLM(agg@W_out+b)) ---------------------
__global__ void __launch_bounds__(512, 1) k_out(
    const float* __restrict__ node,
    const float* __restrict__ Wout, const float* __restrict__ bout,
    const float* __restrict__ normw, const float* __restrict__ normb,
    float* __restrict__ out, int n_nodes)
{
    extern __shared__ float sm[];
    float* W_s = sm;                  // 16384 floats
    float* shx = sm + 16384;          // [HID][TPADP] transposed tile
    int tid = threadIdx.x;
    int tx = tid & 31;
    int ty = tid >> 5;
    int base = blockIdx.x * TM;
    int tx4 = tx * 4;
    int r0 = ty * 8;

    const float4* Wg = (const float4*)Wout;
    #pragma unroll
    for (int i = tid; i < 4096; i += 512)
        ((float4*)W_s)[i] = __ldg(&Wg[i]);

    for (int i = tid; i < TM * 32; i += 512) {
        int r  = i >> 5;
        int c4 = (i & 31) * 4;
        int row = base + r;
        float4 v = make_float4(0.f, 0.f, 0.f, 0.f);
        if (row < n_nodes) v = *(const float4*)&g_agg[(size_t)row * HID + c4];
        shx[(c4 + 0) * TPADP + r] = v.x; shx[(c4 + 1) * TPADP + r] = v.y;
        shx[(c4 + 2) * TPADP + r] = v.z; shx[(c4 + 3) * TPADP + r] = v.w;
    }
    __syncthreads();

    u64 acc[4][4];
    #pragma unroll
    for (int p = 0; p < 4; p++)
        #pragma unroll
        for (int c = 0; c < 4; c++) acc[p][c] = 0ull;

    #pragma unroll 8
    for (int k = 0; k < HID; k++) {
        float4 w = *(const float4*)&W_s[k * HID + tx4];
        const float* xrow = &shx[k * TPADP + r0];
        u64 x2[4];
        x2[0] = *(const u64*)&xrow[0];
        x2[1] = *(const u64*)&xrow[2];
        x2[2] = *(const u64*)&xrow[4];
        x2[3] = *(const u64*)&xrow[6];
        u64 w0 = pk2(w.x, w.x), w1 = pk2(w.y, w.y),
            w2 = pk2(w.z, w.z), w3 = pk2(w.w, w.w);
        #pragma unroll
        for (int p = 0; p < 4; p++) {
            acc[p][0] = fma2(x2[p], w0, acc[p][0]);
            acc[p][1] = fma2(x2[p], w1, acc[p][1]);
            acc[p][2] = fma2(x2[p], w2, acc[p][2]);
            acc[p][3] = fma2(x2[p], w3, acc[p][3]);
        }
    }

    // epilogue: FiLM + residual + LayerNorm, all within the warp
    float4 bo4 = __ldg(&((const float4*)bout)[tx]);
    float4 gm4 = *(const float4*)&g_gamma[tx4];
    float4 bt4 = *(const float4*)&g_beta[tx4];
    float4 nw4 = __ldg(&((const float4*)normw)[tx]);
    float4 nb4 = __ldg(&((const float4*)normb)[tx]);

    #pragma unroll
    for (int p = 0; p < 4; p++) {
        #pragma unroll
        for (int h = 0; h < 2; h++) {
            int row = base + r0 + 2 * p + h;
            bool ok = (row < n_nodes);
            float4 nd = make_float4(0.f, 0.f, 0.f, 0.f);
            if (ok) nd = *(const float4*)&node[(size_t)row * HID + tx4];
            float lo, hi, y0, y1, y2, y3;
            unpk2(acc[p][0], lo, hi); y0 = nd.x + ((h ? hi : lo) + bo4.x) * gm4.x + bt4.x;
            unpk2(acc[p][1], lo, hi); y1 = nd.y + ((h ? hi : lo) + bo4.y) * gm4.y + bt4.y;
            unpk2(acc[p][2], lo, hi); y2 = nd.z + ((h ? hi : lo) + bo4.z) * gm4.z + bt4.z;
            unpk2(acc[p][3], lo, hi); y3 = nd.w + ((h ? hi : lo) + bo4.w) * gm4.w + bt4.w;

            float s1 = y0 + y1 + y2 + y3;
            float s2 = y0 * y0 + y1 * y1 + y2 * y2 + y3 * y3;
            #pragma unroll
            for (int off = 16; off; off >>= 1) {
                s1 += __shfl_xor_sync(0xffffffffu, s1, off);
                s2 += __shfl_xor_sync(0xffffffffu, s2, off);
            }
            float mu  = s1 * (1.0f / HID);
            float var = s2 * (1.0f / HID) - mu * mu;
            float inv = rsqrtf(var + 1e-5f);
            if (ok) {
                float4 o;
                o.x = (y0 - mu) * inv * nw4.x + nb4.x;
                o.y = (y1 - mu) * inv * nw4.y + nb4.y;
                o.z = (y2 - mu) * inv * nw4.z + nb4.z;
                o.w = (y3 - mu) * inv * nw4.w + nb4.w;
                *(float4*)&out[(size_t)row * HID + tx4] = o;
            }
        }
    }
}

// ---------------- launch -----------------------------------------------------
extern "C" void kernel_launch(void* const* d_in, const int* in_sizes, int n_in,
                              void* d_out, int out_size)
{
    const float* node   = (const float*)d_in[0];
    const int*   eidx   = (const int*)  d_in[1];
    const int*   etype  = (const int*)  d_in[2];
    const float* task   = (const float*)d_in[3];
    const float* Wsrc   = (const float*)d_in[4];
    const float* bsrc   = (const float*)d_in[5];
    const float* Wdst   = (const float*)d_in[6];
    const float* bdst   = (const float*)d_in[7];
    const float* eemb   = (const float*)d_in[8];
    const float* att    = (const float*)d_in[9];
    const float* Wout   = (const float*)d_in[10];
    const float* bout   = (const float*)d_in[11];
    const float* normw  = (const float*)d_in[12];
    const float* normb  = (const float*)d_in[13];
    const float* Wfilm  = (const float*)d_in[14];
    const float* bfilm  = (const float*)d_in[15];
    float* out = (float*)d_out;

    int n_nodes = in_sizes[0] / HID;
    int n_edges = in_sizes[2];
    const int* src = eidx;
    const int* dst = eidx + n_edges;

    const int smem_proj = (2 * 16384 + HID * TPADP) * sizeof(float);  // ~197KB
    const int smem_out  = (16384 + HID * TPADP) * sizeof(float);      // ~131KB
    cudaFuncSetAttribute(k_proj, cudaFuncAttributeMaxDynamicSharedMemorySize, smem_proj);
    cudaFuncSetAttribute(k_out,  cudaFuncAttributeMaxDynamicSharedMemorySize, smem_out);

    int gblk = (n_nodes + TM - 1) / TM;
    int nsb  = (n_nodes + 1023) / 1024;

    // fork: side stream builds the CSR (independent of the GEMMs)
    cudaEventRecord(g_evFork, 0);
    cudaStreamWaitEvent(g_s2, g_evFork, 0);

    k_zero<<<nsb, 1024, 0, g_s2>>>(n_nodes);                         // kernel 0
    k_hist<<<(n_edges + 255) / 256, 256, 0, g_s2>>>(dst, n_edges);   // kernel 1
    // main stream: FiLM + projection GEMM (proj = 4th kernel -> profiled)
    k_film<<<1, 2 * HID>>>(task, Wfilm, bfilm);                      // kernel 2
    k_proj<<<gblk, 512, smem_proj>>>(node, Wsrc, bsrc, Wdst, bdst,   // kernel 3
                                     n_nodes);
    // side stream continues the CSR build
    k_scan1<<<nsb, 1024, 0, g_s2>>>(n_nodes);
    k_scan2<<<nsb, 1024, 0, g_s2>>>(n_nodes);
    k_scatter<<<(n_edges + 255) / 256, 256, 0, g_s2>>>(src, dst, etype, n_edges);
    cudaEventRecord(g_evJoin, g_s2);

    // join: edge needs proj outputs AND the CSR
    cudaStreamWaitEvent(0, g_evJoin, 0);
    k_edge<<<(n_nodes * 32 + 255) / 256, 256>>>(eemb, att, n_nodes);
    k_out<<<gblk, 512, smem_out>>>(node, Wout, bout, normw, normb, out, n_nodes);
}